// round 1
// baseline (speedup 1.0000x reference)
#include <cuda_runtime.h>
#include <cuda_bf16.h>
#include <cstdint>

// Problem constants (shape-verified at launch)
#define D 64
#define MAX_T 32768
#define MAX_N 8192

// ---------------- scratch (no allocs allowed) ----------------
__device__ float g_en  [MAX_N * D];     // normalized codebook [N][D]
__device__ float g_enT [D * MAX_N];     // transposed          [D][N]
__device__ float g_en2 [MAX_N];         // sum(en*en) per code (post-normalization)
__device__ float g_zf  [MAX_T * D];     // normalized tokens   [T][D]
__device__ float g_zfT [D * MAX_T];     // transposed          [D][T]
__device__ float g_zf2 [MAX_T];         // sum(zf*zf) per token
__device__ int   g_idx [MAX_T];
__device__ float g_part[MAX_T / 16];    // per-block loss partials
__device__ float g_dump_zq [MAX_T * D]; // fallback sinks if out layout differs
__device__ float g_dump_idx[MAX_T];
__device__ float g_dump_loss[1];

// ---------------- row-normalize (warp per row of 64) ----------------
__global__ void k_norm(const float* __restrict__ x, float* __restrict__ y,
                       float* __restrict__ yT, float* __restrict__ y2,
                       int rows, int ldT) {
    int r    = blockIdx.x * 8 + (threadIdx.x >> 5);
    int lane = threadIdx.x & 31;
    if (r >= rows) return;
    float x0 = x[(size_t)r * D + lane];
    float x1 = x[(size_t)r * D + lane + 32];
    float ss = x0 * x0 + x1 * x1;
    #pragma unroll
    for (int off = 16; off; off >>= 1) ss += __shfl_xor_sync(0xffffffffu, ss, off);
    float nrm = sqrtf(ss);
    float dn  = fmaxf(nrm, 1e-12f);
    float y0 = x0 / dn, y1 = x1 / dn;
    y[(size_t)r * D + lane]      = y0;
    y[(size_t)r * D + lane + 32] = y1;
    yT[(size_t)lane * ldT + r]        = y0;
    yT[(size_t)(lane + 32) * ldT + r] = y1;
    float s2 = y0 * y0 + y1 * y1;
    #pragma unroll
    for (int off = 16; off; off >>= 1) s2 += __shfl_xor_sync(0xffffffffu, s2, off);
    if (lane == 0) y2[r] = s2;
}

// ---------------- fused GEMM + argmin ----------------
// Block tile: BM=128 tokens x BN=64 codes, K=D=64 (full). 256 threads, 8x4 micro-tile.
#define BM 128
#define BN 64
#define TMt 8
#define TNt 4

__global__ __launch_bounds__(256, 2)
void k_argmin(const float* __restrict__ zfT, const float* __restrict__ enT,
              const float* __restrict__ zf2, const float* __restrict__ en2,
              int* __restrict__ idx_out, int T, int N) {
    __shared__ float smA[D * BM]; // [k][m]  32 KB
    __shared__ float smB[D * BN]; // [k][n]  16 KB
    const int tid = threadIdx.x;
    const int tx = tid & 15;      // code group  (4 codes)
    const int ty = tid >> 4;      // token group (8 tokens)
    const int m0 = blockIdx.x * BM;

    // Load token tile once: zfT[k*T + m0+m] -> smA[k*BM + m]  (float4, coalesced, conflict-free)
    for (int i = tid; i < D * BM / 4; i += 256) {
        int k = i / (BM / 4), mq = i % (BM / 4);
        *(float4*)&smA[k * BM + mq * 4] = *(const float4*)&zfT[(size_t)k * T + m0 + mq * 4];
    }

    float best_d[TMt];
    int   best_i[TMt];
    float a2[TMt];
    #pragma unroll
    for (int i = 0; i < TMt; i++) {
        best_d[i] = 3.4e38f; best_i[i] = 0;
        a2[i] = zf2[m0 + ty * TMt + i];
    }

    for (int n0 = 0; n0 < N; n0 += BN) {
        __syncthreads(); // protects smB reuse (and smA fill on first iter)
        for (int i = tid; i < D * BN / 4; i += 256) {
            int k = i / (BN / 4), nq = i % (BN / 4);
            *(float4*)&smB[k * BN + nq * 4] = *(const float4*)&enT[(size_t)k * N + n0 + nq * 4];
        }
        __syncthreads();

        float acc[TMt][TNt];
        #pragma unroll
        for (int mi = 0; mi < TMt; mi++)
            #pragma unroll
            for (int ni = 0; ni < TNt; ni++) acc[mi][ni] = 0.f;

        #pragma unroll 16
        for (int k = 0; k < D; k++) {
            float4 b4 = *(const float4*)&smB[k * BN + tx * TNt];
            float4 a0 = *(const float4*)&smA[k * BM + ty * TMt];
            float4 a1 = *(const float4*)&smA[k * BM + ty * TMt + 4];
            float a[TMt] = {a0.x, a0.y, a0.z, a0.w, a1.x, a1.y, a1.z, a1.w};
            float b[TNt] = {b4.x, b4.y, b4.z, b4.w};
            #pragma unroll
            for (int mi = 0; mi < TMt; mi++)
                #pragma unroll
                for (int ni = 0; ni < TNt; ni++)
                    acc[mi][ni] = fmaf(a[mi], b[ni], acc[mi][ni]);
        }

        // epilogue: d = (zf2 + en2) - 2*dot ; running argmin (strict <, codes ascend -> first-min)
        #pragma unroll
        for (int ni = 0; ni < TNt; ni++) {
            int n = n0 + tx * TNt + ni;
            float e2 = en2[n];
            #pragma unroll
            for (int mi = 0; mi < TMt; mi++) {
                float d = (a2[mi] + e2) - 2.0f * acc[mi][ni];
                if (d < best_d[mi]) { best_d[mi] = d; best_i[mi] = n; }
            }
        }
    }

    // reduce across the 16 tx lanes (same ty -> contiguous 16 lanes in a warp)
    #pragma unroll
    for (int mi = 0; mi < TMt; mi++) {
        float d = best_d[mi]; int bi = best_i[mi];
        #pragma unroll
        for (int off = 8; off; off >>= 1) {
            float d2 = __shfl_xor_sync(0xffffffffu, d, off);
            int   i2 = __shfl_xor_sync(0xffffffffu, bi, off);
            if (d2 < d || (d2 == d && i2 < bi)) { d = d2; bi = i2; }
        }
        if (tx == 0) idx_out[m0 + ty * TMt + mi] = bi;
    }
}

// ---------------- gather + STE output + loss partials ----------------
// 16 threads per token (quad q covers d = 4q..4q+3), 16 tokens per block.
__global__ void k_gather(const float* __restrict__ z, const float* __restrict__ en,
                         const float* __restrict__ zf, const int* __restrict__ idx,
                         float* __restrict__ out_zq, float* __restrict__ out_idx,
                         float* __restrict__ partial) {
    int tid = threadIdx.x;
    int token = blockIdx.x * 16 + (tid >> 4);
    int q = tid & 15;
    int c = idx[token];
    float4 e  = ((const float4*)&en[(size_t)c * D])[q];
    float4 zz = ((const float4*)&z [(size_t)token * D])[q];
    float4 f  = ((const float4*)&zf[(size_t)token * D])[q];
    float4 o;
    o.x = zz.x + (e.x - zz.x); o.y = zz.y + (e.y - zz.y);
    o.z = zz.z + (e.z - zz.z); o.w = zz.w + (e.w - zz.w);
    ((float4*)&out_zq[(size_t)token * D])[q] = o;
    float dx = e.x - f.x, dy = e.y - f.y, dz = e.z - f.z, dw = e.w - f.w;
    float lsum = dx * dx + dy * dy + dz * dz + dw * dw;
    if (q == 0) out_idx[token] = (float)c;

    __shared__ float red[256];
    red[tid] = lsum;
    __syncthreads();
    #pragma unroll
    for (int s = 128; s > 0; s >>= 1) {
        if (tid < s) red[tid] += red[tid + s];
        __syncthreads();
    }
    if (tid == 0) partial[blockIdx.x] = red[0];
}

__global__ void k_loss(const float* __restrict__ partial, int nPart,
                       float* __restrict__ out_loss, float denomN) {
    __shared__ float red[256];
    int tid = threadIdx.x;
    float s = 0.f;
    for (int i = tid; i < nPart; i += 256) s += partial[i]; // fixed order -> deterministic
    red[tid] = s;
    __syncthreads();
    #pragma unroll
    for (int st = 128; st > 0; st >>= 1) {
        if (tid < st) red[tid] += red[tid + st];
        __syncthreads();
    }
    if (tid == 0) {
        float m = red[0] / denomN;
        out_loss[0] = 0.25f * m + m; // BETA*mean + mean
    }
}

// ---------------- launcher ----------------
extern "C" void kernel_launch(void* const* d_in, const int* in_sizes, int n_in,
                              void* d_out, int out_size) {
    const float* z  = (const float*)d_in[0];
    const float* cb = (const float*)d_in[1];
    const int T = in_sizes[0] / D;   // 32768
    const int N = in_sizes[1] / D;   // 8192
    if (T > MAX_T || N > MAX_N || (T % BM) || (N % BN)) return;

    float* out = (float*)d_out;
    const int ZQ = T * D;

    float *en, *enT, *en2, *zf, *zfT, *zf2, *part, *dzq, *didx, *dloss;
    int* didx_i;
    cudaGetSymbolAddress((void**)&en,   g_en);
    cudaGetSymbolAddress((void**)&enT,  g_enT);
    cudaGetSymbolAddress((void**)&en2,  g_en2);
    cudaGetSymbolAddress((void**)&zf,   g_zf);
    cudaGetSymbolAddress((void**)&zfT,  g_zfT);
    cudaGetSymbolAddress((void**)&zf2,  g_zf2);
    cudaGetSymbolAddress((void**)&part, g_part);
    cudaGetSymbolAddress((void**)&didx_i, g_idx);
    cudaGetSymbolAddress((void**)&dzq,  g_dump_zq);
    cudaGetSymbolAddress((void**)&didx, g_dump_idx);
    cudaGetSymbolAddress((void**)&dloss, g_dump_loss);

    // Output layout: concat(z_q_out [T*D], loss [1], idx-as-float [T]); fall back by size.
    float *o_zq = dzq, *o_loss = dloss, *o_idx = didx;
    if (out_size >= ZQ + 1 + T) { o_zq = out; o_loss = out + ZQ; o_idx = out + ZQ + 1; }
    else if (out_size == ZQ)    { o_zq = out; }
    else if (out_size == T)     { o_idx = out; }
    else if (out_size == 1)     { o_loss = out; }

    k_norm<<<(N + 7) / 8, 256>>>(cb, en, enT, en2, N, N);
    k_norm<<<(T + 7) / 8, 256>>>(z, zf, zfT, zf2, T, T);
    k_argmin<<<T / BM, 256>>>(zfT, enT, zf2, en2, didx_i, T, N);
    k_gather<<<T / 16, 256>>>(z, en, zf, didx_i, o_zq, o_idx, part);
    k_loss<<<1, 256>>>(part, T / 16, o_loss, (float)(T * D));
}

// round 2
// speedup vs baseline: 1.0000x; 1.0000x over previous
#include <cuda_runtime.h>
#include <cuda_bf16.h>
#include <cstdint>

// Problem constants (shape-verified at launch)
#define D 64
#define MAX_T 32768
#define MAX_N 8192

// ---------------- scratch (no allocs allowed) ----------------
__device__ float g_en  [MAX_N * D];     // normalized codebook [N][D]
__device__ float g_enT [D * MAX_N];     // transposed          [D][N]
__device__ float g_en2 [MAX_N];         // sum(en*en) per code (post-normalization)
__device__ float g_zf  [MAX_T * D];     // normalized tokens   [T][D]
__device__ float g_zfT [D * MAX_T];     // transposed          [D][T]
__device__ float g_zf2 [MAX_T];         // sum(zf*zf) per token
__device__ int   g_idx [MAX_T];
__device__ float g_part[MAX_T / 16];    // per-block loss partials
__device__ float g_dump_zq [MAX_T * D]; // fallback sinks if out layout differs
__device__ float g_dump_idx[MAX_T];
__device__ float g_dump_loss[1];

// ---------------- row-normalize (warp per row of 64) ----------------
__global__ void k_norm(const float* __restrict__ x, float* __restrict__ y,
                       float* __restrict__ yT, float* __restrict__ y2,
                       int rows, int ldT) {
    int r    = blockIdx.x * 8 + (threadIdx.x >> 5);
    int lane = threadIdx.x & 31;
    if (r >= rows) return;
    float x0 = x[(size_t)r * D + lane];
    float x1 = x[(size_t)r * D + lane + 32];
    float ss = x0 * x0 + x1 * x1;
    #pragma unroll
    for (int off = 16; off; off >>= 1) ss += __shfl_xor_sync(0xffffffffu, ss, off);
    float nrm = sqrtf(ss);
    float dn  = fmaxf(nrm, 1e-12f);
    float y0 = x0 / dn, y1 = x1 / dn;
    y[(size_t)r * D + lane]      = y0;
    y[(size_t)r * D + lane + 32] = y1;
    yT[(size_t)lane * ldT + r]        = y0;
    yT[(size_t)(lane + 32) * ldT + r] = y1;
    float s2 = y0 * y0 + y1 * y1;
    #pragma unroll
    for (int off = 16; off; off >>= 1) s2 += __shfl_xor_sync(0xffffffffu, s2, off);
    if (lane == 0) y2[r] = s2;
}

// ---------------- fused GEMM + argmin ----------------
// Block tile: BM=128 tokens x BN=64 codes, K=D=64 (full). 256 threads, 8x4 micro-tile.
#define BM 128
#define BN 64
#define TMt 8
#define TNt 4

__global__ __launch_bounds__(256, 2)
void k_argmin(const float* __restrict__ zfT, const float* __restrict__ enT,
              const float* __restrict__ zf2, const float* __restrict__ en2,
              int* __restrict__ idx_out, int T, int N) {
    __shared__ float smA[D * BM]; // [k][m]  32 KB
    __shared__ float smB[D * BN]; // [k][n]  16 KB
    const int tid = threadIdx.x;
    const int tx = tid & 15;      // code group  (4 codes)
    const int ty = tid >> 4;      // token group (8 tokens)
    const int m0 = blockIdx.x * BM;

    // Load token tile once: zfT[k*T + m0+m] -> smA[k*BM + m]  (float4, coalesced, conflict-free)
    for (int i = tid; i < D * BM / 4; i += 256) {
        int k = i / (BM / 4), mq = i % (BM / 4);
        *(float4*)&smA[k * BM + mq * 4] = *(const float4*)&zfT[(size_t)k * T + m0 + mq * 4];
    }

    float best_d[TMt];
    int   best_i[TMt];
    float a2[TMt];
    #pragma unroll
    for (int i = 0; i < TMt; i++) {
        best_d[i] = 3.4e38f; best_i[i] = 0;
        a2[i] = zf2[m0 + ty * TMt + i];
    }

    for (int n0 = 0; n0 < N; n0 += BN) {
        __syncthreads(); // protects smB reuse (and smA fill on first iter)
        for (int i = tid; i < D * BN / 4; i += 256) {
            int k = i / (BN / 4), nq = i % (BN / 4);
            *(float4*)&smB[k * BN + nq * 4] = *(const float4*)&enT[(size_t)k * N + n0 + nq * 4];
        }
        __syncthreads();

        float acc[TMt][TNt];
        #pragma unroll
        for (int mi = 0; mi < TMt; mi++)
            #pragma unroll
            for (int ni = 0; ni < TNt; ni++) acc[mi][ni] = 0.f;

        #pragma unroll 16
        for (int k = 0; k < D; k++) {
            float4 b4 = *(const float4*)&smB[k * BN + tx * TNt];
            float4 a0 = *(const float4*)&smA[k * BM + ty * TMt];
            float4 a1 = *(const float4*)&smA[k * BM + ty * TMt + 4];
            float a[TMt] = {a0.x, a0.y, a0.z, a0.w, a1.x, a1.y, a1.z, a1.w};
            float b[TNt] = {b4.x, b4.y, b4.z, b4.w};
            #pragma unroll
            for (int mi = 0; mi < TMt; mi++)
                #pragma unroll
                for (int ni = 0; ni < TNt; ni++)
                    acc[mi][ni] = fmaf(a[mi], b[ni], acc[mi][ni]);
        }

        // epilogue: d = (zf2 + en2) - 2*dot ; running argmin (strict <, codes ascend -> first-min)
        #pragma unroll
        for (int ni = 0; ni < TNt; ni++) {
            int n = n0 + tx * TNt + ni;
            float e2 = en2[n];
            #pragma unroll
            for (int mi = 0; mi < TMt; mi++) {
                float d = (a2[mi] + e2) - 2.0f * acc[mi][ni];
                if (d < best_d[mi]) { best_d[mi] = d; best_i[mi] = n; }
            }
        }
    }

    // reduce across the 16 tx lanes (same ty -> contiguous 16 lanes in a warp)
    #pragma unroll
    for (int mi = 0; mi < TMt; mi++) {
        float d = best_d[mi]; int bi = best_i[mi];
        #pragma unroll
        for (int off = 8; off; off >>= 1) {
            float d2 = __shfl_xor_sync(0xffffffffu, d, off);
            int   i2 = __shfl_xor_sync(0xffffffffu, bi, off);
            if (d2 < d || (d2 == d && i2 < bi)) { d = d2; bi = i2; }
        }
        if (tx == 0) idx_out[m0 + ty * TMt + mi] = bi;
    }
}

// ---------------- gather + STE output + loss partials ----------------
// 16 threads per token (quad q covers d = 4q..4q+3), 16 tokens per block.
__global__ void k_gather(const float* __restrict__ z, const float* __restrict__ en,
                         const float* __restrict__ zf, const int* __restrict__ idx,
                         float* __restrict__ out_zq, float* __restrict__ out_idx,
                         float* __restrict__ partial) {
    int tid = threadIdx.x;
    int token = blockIdx.x * 16 + (tid >> 4);
    int q = tid & 15;
    int c = idx[token];
    float4 e  = ((const float4*)&en[(size_t)c * D])[q];
    float4 zz = ((const float4*)&z [(size_t)token * D])[q];
    float4 f  = ((const float4*)&zf[(size_t)token * D])[q];
    float4 o;
    o.x = zz.x + (e.x - zz.x); o.y = zz.y + (e.y - zz.y);
    o.z = zz.z + (e.z - zz.z); o.w = zz.w + (e.w - zz.w);
    ((float4*)&out_zq[(size_t)token * D])[q] = o;
    float dx = e.x - f.x, dy = e.y - f.y, dz = e.z - f.z, dw = e.w - f.w;
    float lsum = dx * dx + dy * dy + dz * dz + dw * dw;
    if (q == 0) out_idx[token] = (float)c;

    __shared__ float red[256];
    red[tid] = lsum;
    __syncthreads();
    #pragma unroll
    for (int s = 128; s > 0; s >>= 1) {
        if (tid < s) red[tid] += red[tid + s];
        __syncthreads();
    }
    if (tid == 0) partial[blockIdx.x] = red[0];
}

__global__ void k_loss(const float* __restrict__ partial, int nPart,
                       float* __restrict__ out_loss, float denomN) {
    __shared__ float red[256];
    int tid = threadIdx.x;
    float s = 0.f;
    for (int i = tid; i < nPart; i += 256) s += partial[i]; // fixed order -> deterministic
    red[tid] = s;
    __syncthreads();
    #pragma unroll
    for (int st = 128; st > 0; st >>= 1) {
        if (tid < st) red[tid] += red[tid + st];
        __syncthreads();
    }
    if (tid == 0) {
        float m = red[0] / denomN;
        out_loss[0] = 0.25f * m + m; // BETA*mean + mean
    }
}

// ---------------- launcher ----------------
extern "C" void kernel_launch(void* const* d_in, const int* in_sizes, int n_in,
                              void* d_out, int out_size) {
    const float* z  = (const float*)d_in[0];
    const float* cb = (const float*)d_in[1];
    const int T = in_sizes[0] / D;   // 32768
    const int N = in_sizes[1] / D;   // 8192
    if (T > MAX_T || N > MAX_N || (T % BM) || (N % BN)) return;

    float* out = (float*)d_out;
    const int ZQ = T * D;

    float *en, *enT, *en2, *zf, *zfT, *zf2, *part, *dzq, *didx, *dloss;
    int* didx_i;
    cudaGetSymbolAddress((void**)&en,   g_en);
    cudaGetSymbolAddress((void**)&enT,  g_enT);
    cudaGetSymbolAddress((void**)&en2,  g_en2);
    cudaGetSymbolAddress((void**)&zf,   g_zf);
    cudaGetSymbolAddress((void**)&zfT,  g_zfT);
    cudaGetSymbolAddress((void**)&zf2,  g_zf2);
    cudaGetSymbolAddress((void**)&part, g_part);
    cudaGetSymbolAddress((void**)&didx_i, g_idx);
    cudaGetSymbolAddress((void**)&dzq,  g_dump_zq);
    cudaGetSymbolAddress((void**)&didx, g_dump_idx);
    cudaGetSymbolAddress((void**)&dloss, g_dump_loss);

    // Output layout: concat(z_q_out [T*D], loss [1], idx-as-float [T]); fall back by size.
    float *o_zq = dzq, *o_loss = dloss, *o_idx = didx;
    if (out_size >= ZQ + 1 + T) { o_zq = out; o_loss = out + ZQ; o_idx = out + ZQ + 1; }
    else if (out_size == ZQ)    { o_zq = out; }
    else if (out_size == T)     { o_idx = out; }
    else if (out_size == 1)     { o_loss = out; }

    k_norm<<<(N + 7) / 8, 256>>>(cb, en, enT, en2, N, N);
    k_norm<<<(T + 7) / 8, 256>>>(z, zf, zfT, zf2, T, T);
    k_argmin<<<T / BM, 256>>>(zfT, enT, zf2, en2, didx_i, T, N);
    k_gather<<<T / 16, 256>>>(z, en, zf, didx_i, o_zq, o_idx, part);
    k_loss<<<1, 256>>>(part, T / 16, o_loss, (float)(T * D));
}